// round 1
// baseline (speedup 1.0000x reference)
#include <cuda_runtime.h>
#include <math.h>

#define N_HEADN 100000
#define N_TAILN 100000
#define NE      1600000
#define INF_    128
#define NHEADS  4
#define FDIM    128          // NHEADS * OUT
#define SLOPE   0.2f
#define N_ETYPES 8

// ---------------- scratch (static device globals; no allocation) -------------
__device__ float g_h_tail[(size_t)N_TAILN * FDIM];   // 51.2 MB
__device__ float g_hl[(size_t)N_HEADN * NHEADS];
__device__ float g_hr[(size_t)N_TAILN * NHEADS];
__device__ float g_he[N_ETYPES * NHEADS];
__device__ float g_WAl[INF_ * NHEADS];
__device__ float g_WAr[INF_ * NHEADS];
__device__ float g_att[(size_t)NE * NHEADS];         // 25.6 MB
__device__ int   g_deg[N_HEADN];
__device__ int   g_off[N_HEADN + 1];
__device__ int   g_cur[N_HEADN];
__device__ int   g_es[NE];                           // 6.4 MB

// ---------------- tiny setup: fold a_l/a_r into W, compute he ---------------
__global__ void k_setup(const float* __restrict__ W, const float* __restrict__ We,
                        const float* __restrict__ a_l, const float* __restrict__ a_r,
                        const float* __restrict__ a_e, const float* __restrict__ emb) {
    int t = threadIdx.x;             // 128 threads: one per input-feature row
    #pragma unroll
    for (int h = 0; h < NHEADS; h++) {
        float sl = 0.f, sr = 0.f;
        #pragma unroll
        for (int d = 0; d < 32; d++) {
            float w = W[t * FDIM + h * 32 + d];
            sl += w * a_l[h * 32 + d];
            sr += w * a_r[h * 32 + d];
        }
        g_WAl[t * NHEADS + h] = sl;
        g_WAr[t * NHEADS + h] = sr;
    }
    if (t < N_ETYPES * NHEADS) {
        int ty = t >> 2, h = t & 3;
        float s = 0.f;
        for (int de = 0; de < 32; de++) {
            float ev = 0.f;
            for (int k = 0; k < 32; k++)
                ev += emb[ty * 32 + k] * We[k * 128 + h * 32 + de];
            s += a_e[h * 32 + de] * ev;
        }
        g_he[t] = s;
    }
}

// ---------------- GEMM: g_h_tail = tail_feature(100000x128) @ W(128x128) ----
// 64x128 block tile, K-tile 64, each thread 4x8 register tile. 256 thr/block.
__global__ void __launch_bounds__(256) k_gemm(const float* __restrict__ A,
                                              const float* __restrict__ W) {
    __shared__ float As[64 * 64];    // 16 KB
    __shared__ float Ws[64 * 128];   // 32 KB
    int t  = threadIdx.x;
    int ti = t >> 4;                 // 0..15 row group
    int tj = t & 15;                 // 0..15 col group
    int row0 = blockIdx.x * 64;

    float acc[4][8];
    #pragma unroll
    for (int i = 0; i < 4; i++)
        #pragma unroll
        for (int j = 0; j < 8; j++) acc[i][j] = 0.f;

    for (int k0 = 0; k0 < 128; k0 += 64) {
        // load A tile 64x64
        #pragma unroll
        for (int p = t; p < 1024; p += 256) {
            int r = p >> 4, c = (p & 15) << 2;
            int gr = row0 + r;
            float4 v = make_float4(0.f, 0.f, 0.f, 0.f);
            if (gr < N_TAILN) v = *(const float4*)&A[(size_t)gr * 128 + k0 + c];
            *(float4*)&As[r * 64 + c] = v;
        }
        // load W tile 64x128
        #pragma unroll
        for (int p = t; p < 2048; p += 256) {
            int r = p >> 5, c = (p & 31) << 2;
            *(float4*)&Ws[r * 128 + c] = *(const float4*)&W[(k0 + r) * 128 + c];
        }
        __syncthreads();
        const float* ap = &As[(ti * 4) * 64];
        const float* wp = &Ws[tj * 8];
        #pragma unroll 8
        for (int k = 0; k < 64; k++) {
            float a0 = ap[0 * 64 + k];
            float a1 = ap[1 * 64 + k];
            float a2 = ap[2 * 64 + k];
            float a3 = ap[3 * 64 + k];
            float4 b0 = *(const float4*)&wp[k * 128];
            float4 b1 = *(const float4*)&wp[k * 128 + 4];
            acc[0][0] += a0 * b0.x; acc[0][1] += a0 * b0.y; acc[0][2] += a0 * b0.z; acc[0][3] += a0 * b0.w;
            acc[0][4] += a0 * b1.x; acc[0][5] += a0 * b1.y; acc[0][6] += a0 * b1.z; acc[0][7] += a0 * b1.w;
            acc[1][0] += a1 * b0.x; acc[1][1] += a1 * b0.y; acc[1][2] += a1 * b0.z; acc[1][3] += a1 * b0.w;
            acc[1][4] += a1 * b1.x; acc[1][5] += a1 * b1.y; acc[1][6] += a1 * b1.z; acc[1][7] += a1 * b1.w;
            acc[2][0] += a2 * b0.x; acc[2][1] += a2 * b0.y; acc[2][2] += a2 * b0.z; acc[2][3] += a2 * b0.w;
            acc[2][4] += a2 * b1.x; acc[2][5] += a2 * b1.y; acc[2][6] += a2 * b1.z; acc[2][7] += a2 * b1.w;
            acc[3][0] += a3 * b0.x; acc[3][1] += a3 * b0.y; acc[3][2] += a3 * b0.z; acc[3][3] += a3 * b0.w;
            acc[3][4] += a3 * b1.x; acc[3][5] += a3 * b1.y; acc[3][6] += a3 * b1.z; acc[3][7] += a3 * b1.w;
        }
        __syncthreads();
    }
    #pragma unroll
    for (int rr = 0; rr < 4; rr++) {
        int gr = row0 + ti * 4 + rr;
        if (gr < N_TAILN) {
            float4 o0 = make_float4(acc[rr][0], acc[rr][1], acc[rr][2], acc[rr][3]);
            float4 o1 = make_float4(acc[rr][4], acc[rr][5], acc[rr][6], acc[rr][7]);
            *(float4*)&g_h_tail[(size_t)gr * 128 + tj * 8]     = o0;
            *(float4*)&g_h_tail[(size_t)gr * 128 + tj * 8 + 4] = o1;
        }
    }
}

// ---------------- hr[n,h] = sum_d h_tail[n,h*32+d] * a_r[h,d] ---------------
__global__ void k_hr(const float* __restrict__ a_r) {
    int gt = blockIdx.x * blockDim.x + threadIdx.x;
    int n = gt >> 5, lane = gt & 31;
    if (n >= N_TAILN) return;
    float4 v  = *(const float4*)&g_h_tail[(size_t)n * 128 + lane * 4];
    float4 ar = *(const float4*)&a_r[lane * 4];
    float p = v.x * ar.x + v.y * ar.y + v.z * ar.z + v.w * ar.w;
    p += __shfl_xor_sync(0xffffffffu, p, 4);
    p += __shfl_xor_sync(0xffffffffu, p, 2);
    p += __shfl_xor_sync(0xffffffffu, p, 1);
    if ((lane & 7) == 0) g_hr[(size_t)n * 4 + (lane >> 3)] = p;
}

// ---------------- hl = head_feature @ WAl (128x4) ---------------------------
__global__ void k_hl(const float* __restrict__ hf) {
    int gt = blockIdx.x * blockDim.x + threadIdx.x;
    int n = gt >> 5, lane = gt & 31;
    if (n >= N_HEADN) return;
    float4 f = *(const float4*)&hf[(size_t)n * 128 + lane * 4];
    int k = lane * 4;
    float4 w0 = *(const float4*)&g_WAl[(k + 0) * 4];
    float4 w1 = *(const float4*)&g_WAl[(k + 1) * 4];
    float4 w2 = *(const float4*)&g_WAl[(k + 2) * 4];
    float4 w3 = *(const float4*)&g_WAl[(k + 3) * 4];
    float a0 = f.x * w0.x + f.y * w1.x + f.z * w2.x + f.w * w3.x;
    float a1 = f.x * w0.y + f.y * w1.y + f.z * w2.y + f.w * w3.y;
    float a2 = f.x * w0.z + f.y * w1.z + f.z * w2.z + f.w * w3.z;
    float a3 = f.x * w0.w + f.y * w1.w + f.z * w2.w + f.w * w3.w;
    #pragma unroll
    for (int o = 16; o; o >>= 1) {
        a0 += __shfl_xor_sync(0xffffffffu, a0, o);
        a1 += __shfl_xor_sync(0xffffffffu, a1, o);
        a2 += __shfl_xor_sync(0xffffffffu, a2, o);
        a3 += __shfl_xor_sync(0xffffffffu, a3, o);
    }
    if (lane == 0) {
        float4 o = make_float4(a0, a1, a2, a3);
        *(float4*)&g_hl[(size_t)n * 4] = o;
    }
}

// ---------------- CSR build ---------------------------------------------
__global__ void k_zero() {
    int i = blockIdx.x * blockDim.x + threadIdx.x;
    if (i < N_HEADN) g_deg[i] = 0;
}

__global__ void k_hist(const int* __restrict__ el) {
    int e = blockIdx.x * blockDim.x + threadIdx.x;
    if (e < NE) atomicAdd(&g_deg[el[e]], 1);
}

__global__ void k_scan() {
    __shared__ int partial[1024];
    int t = threadIdx.x;
    const int CHUNK = (N_HEADN + 1023) / 1024;
    int start = t * CHUNK;
    int end = min(start + CHUNK, N_HEADN);
    int sum = 0;
    for (int i = start; i < end; i++) sum += g_deg[i];
    partial[t] = sum;
    __syncthreads();
    // inclusive Hillis-Steele scan
    for (int o = 1; o < 1024; o <<= 1) {
        int v = (t >= o) ? partial[t - o] : 0;
        __syncthreads();
        partial[t] += v;
        __syncthreads();
    }
    int run = (t == 0) ? 0 : partial[t - 1];
    for (int i = start; i < end; i++) {
        g_off[i] = run;
        g_cur[i] = run;
        run += g_deg[i];
    }
    if (t == 1023) g_off[N_HEADN] = run;
}

// ---------------- per-edge logits + scatter into CSR ------------------------
__global__ void k_edge(const int* __restrict__ el, const int* __restrict__ et) {
    int e = blockIdx.x * blockDim.x + threadIdx.x;
    if (e >= NE) return;
    int hn = el[e];
    int tn = el[NE + e];
    int ty = et[e];
    float4 l  = *(const float4*)&g_hl[(size_t)hn * 4];
    float4 r  = *(const float4*)&g_hr[(size_t)tn * 4];
    float4 eh = *(const float4*)&g_he[ty * 4];
    float4 a;
    a.x = l.x + r.x + eh.x; if (a.x < 0.f) a.x *= SLOPE;
    a.y = l.y + r.y + eh.y; if (a.y < 0.f) a.y *= SLOPE;
    a.z = l.z + r.z + eh.z; if (a.z < 0.f) a.z *= SLOPE;
    a.w = l.w + r.w + eh.w; if (a.w < 0.f) a.w *= SLOPE;
    *(float4*)&g_att[(size_t)e * 4] = a;
    int pos = atomicAdd(&g_cur[hn], 1);
    g_es[pos] = e;
}

// ---------------- per-node softmax + aggregation ----------------------------
// one block (128 thr) per head node; warp = attention head, lane = out dim
#define CH 128
__global__ void __launch_bounds__(128) k_node(const int* __restrict__ el,
                                              float* __restrict__ out) {
    int n = blockIdx.x;
    int off = g_off[n];
    int deg = g_off[n + 1] - off;
    int tid = threadIdx.x;
    int h = tid >> 5, lane = tid & 31;

    __shared__ int   es_s[CH];
    __shared__ int   tl_s[CH];
    __shared__ float att_s[CH * 4];

    float outv = 0.f;
    if (deg > 0) {
        // pass A: online softmax (m, s) per head
        float m = -1e30f, s = 0.f;
        for (int c0 = 0; c0 < deg; c0 += CH) {
            int cd = min(CH, deg - c0);
            __syncthreads();
            if (tid < cd) es_s[tid] = g_es[off + c0 + tid];
            __syncthreads();
            for (int idx = tid; idx < cd * 4; idx += 128)
                att_s[idx] = g_att[(size_t)es_s[idx >> 2] * 4 + (idx & 3)];
            __syncthreads();
            for (int j = lane; j < cd; j += 32) {
                float a = att_s[j * 4 + h];
                if (a > m) { s *= __expf(m - a); m = a; }
                s += __expf(a - m);
            }
        }
        #pragma unroll
        for (int o = 16; o; o >>= 1) {
            float m2 = __shfl_xor_sync(0xffffffffu, m, o);
            float s2 = __shfl_xor_sync(0xffffffffu, s, o);
            float mn = fmaxf(m, m2);
            s = s * __expf(m - mn) + s2 * __expf(m2 - mn);
            m = mn;
        }
        float inv = 1.f / s;

        // pass B: accumulate alpha-weighted h_tail rows
        for (int c0 = 0; c0 < deg; c0 += CH) {
            int cd = min(CH, deg - c0);
            __syncthreads();
            if (tid < cd) {
                int e = g_es[off + c0 + tid];
                es_s[tid] = e;
                tl_s[tid] = el[NE + e];
            }
            __syncthreads();
            for (int idx = tid; idx < cd * 4; idx += 128)
                att_s[idx] = g_att[(size_t)es_s[idx >> 2] * 4 + (idx & 3)];
            __syncthreads();
            #pragma unroll 4
            for (int j = 0; j < cd; j++) {
                float al = __expf(att_s[j * 4 + h] - m) * inv;
                outv += al * g_h_tail[(size_t)tl_s[j] * 128 + tid];
            }
        }
    }
    // ELU
    out[(size_t)n * 128 + tid] = outv > 0.f ? outv : expm1f(outv);
}

// ---------------- launch -----------------------------------------------------
extern "C" void kernel_launch(void* const* d_in, const int* in_sizes, int n_in,
                              void* d_out, int out_size) {
    const float* head_feature = (const float*)d_in[0];
    const float* tail_feature = (const float*)d_in[1];
    const int*   edge_list    = (const int*)d_in[2];
    const int*   tmp_edge     = (const int*)d_in[3];
    const float* W            = (const float*)d_in[4];
    const float* We           = (const float*)d_in[5];
    const float* a_l          = (const float*)d_in[6];
    const float* a_r          = (const float*)d_in[7];
    const float* a_e          = (const float*)d_in[8];
    const float* emb          = (const float*)d_in[9];
    float* out = (float*)d_out;

    k_setup<<<1, 128>>>(W, We, a_l, a_r, a_e, emb);
    k_gemm<<<(N_TAILN + 63) / 64, 256>>>(tail_feature, W);
    k_hr<<<(N_TAILN * 32 + 255) / 256, 256>>>(a_r);
    k_hl<<<(N_HEADN * 32 + 255) / 256, 256>>>(head_feature);
    k_zero<<<(N_HEADN + 255) / 256, 256>>>();
    k_hist<<<(NE + 255) / 256, 256>>>(edge_list);
    k_scan<<<1, 1024>>>();
    k_edge<<<(NE + 255) / 256, 256>>>(edge_list, tmp_edge);
    k_node<<<N_HEADN, 128>>>(edge_list, out);
}

// round 3
// speedup vs baseline: 1.2564x; 1.2564x over previous
#include <cuda_runtime.h>
#include <math.h>

#define N_HEADN 100000
#define N_TAILN 100000
#define NE      1600000
#define NHEADS  4
#define FDIM    128
#define SLOPE   0.2f
#define N_ETYPES 8
#define GK 32

// ---------------- scratch (static device globals; no allocation) -------------
__device__ float g_h_tail[(size_t)N_TAILN * FDIM];   // 51.2 MB
__device__ float g_hl[(size_t)N_HEADN * NHEADS];
__device__ float g_hr[(size_t)N_TAILN * NHEADS];
__device__ float g_he[N_ETYPES * NHEADS];
__device__ float g_WAl[FDIM * NHEADS];               // W folded with a_l
__device__ float g_Mr[FDIM * NHEADS];                // per-head mask of a_r
__device__ float g_wcsr[(size_t)NE * NHEADS];        // exp-weights in CSR order
__device__ int   g_tl[NE];                           // tail idx in CSR order
__device__ int   g_deg[N_HEADN];
__device__ int   g_off[N_HEADN + 1];
__device__ int   g_cur[N_HEADN];

// ---------------- f32x2 helpers ----------------------------------------------
__device__ __forceinline__ unsigned long long f2pk(float x, float y) {
    unsigned long long r;
    asm("mov.b64 %0, {%1, %2};" : "=l"(r) : "f"(x), "f"(y));
    return r;
}
__device__ __forceinline__ void ffma2(unsigned long long& d, unsigned long long a,
                                      unsigned long long b) {
    asm("fma.rn.f32x2 %0, %1, %2, %3;" : "=l"(d) : "l"(a), "l"(b), "l"(d));
}
__device__ __forceinline__ float2 f2up(unsigned long long v) {
    float2 r;
    asm("mov.b64 {%0, %1}, %2;" : "=f"(r.x), "=f"(r.y) : "l"(v));
    return r;
}

// ---------------- setup: zero deg, fold a_l into W, build Mr, compute he -----
__global__ void k_setup(const float* __restrict__ W, const float* __restrict__ We,
                        const float* __restrict__ a_l, const float* __restrict__ a_r,
                        const float* __restrict__ a_e, const float* __restrict__ emb) {
    int g = blockIdx.x * blockDim.x + threadIdx.x;
    if (g < N_HEADN) g_deg[g] = 0;
    if (blockIdx.x == 0) {
        int t = threadIdx.x;
        if (t < FDIM) {
            #pragma unroll
            for (int h = 0; h < NHEADS; h++) {
                float sl = 0.f;
                #pragma unroll
                for (int d = 0; d < 32; d++)
                    sl += W[t * FDIM + h * 32 + d] * a_l[h * 32 + d];
                g_WAl[t * NHEADS + h] = sl;
                g_Mr[t * NHEADS + h] = ((t >> 5) == h) ? a_r[h * 32 + (t & 31)] : 0.f;
            }
        }
        if (t < N_ETYPES * NHEADS) {
            int ty = t >> 2, h = t & 3;
            float s = 0.f;
            for (int de = 0; de < 32; de++) {
                float ev = 0.f;
                for (int k = 0; k < 32; k++)
                    ev += emb[ty * 32 + k] * We[k * 128 + h * 32 + de];
                s += a_e[h * 32 + de] * ev;
            }
            g_he[t] = s;
        }
    }
}

// ---------------- GEMM: g_h_tail = tail_feature(1e5 x128) @ W(128x128) -------
// 128x128 block tile, 8x8 per thread, f32x2 packed accumulation.
__global__ void __launch_bounds__(256, 2) k_gemm(const float* __restrict__ A,
                                                 const float* __restrict__ W) {
    __shared__ float Ws[GK][128];    // 16 KB, B chunk (k-major)
    __shared__ float As[GK][132];    // 16.9 KB, A chunk transposed [k][row]
    int t  = threadIdx.x;
    int ti = t >> 4;                 // 0..15 -> rows ti*8..+7
    int tj = t & 15;                 // 0..15 -> cols tj*8..+7
    int row0 = blockIdx.x * 128;

    unsigned long long acc[8][4];
    #pragma unroll
    for (int r = 0; r < 8; r++)
        #pragma unroll
        for (int c = 0; c < 4; c++) acc[r][c] = f2pk(0.f, 0.f);

    for (int k0 = 0; k0 < 128; k0 += GK) {
        // load W chunk (32x128), coalesced direct copy
        #pragma unroll
        for (int it = 0; it < 4; it++) {
            int f = t + it * 256;            // 0..1023 float4s
            int k = f >> 5, c4 = f & 31;
            *(float4*)&Ws[k][c4 * 4] = *(const float4*)&W[(k0 + k) * 128 + c4 * 4];
        }
        // load A chunk (128 rows x 32 k) transposed into As[k][row]
        #pragma unroll
        for (int it = 0; it < 4; it++) {
            int f = t + it * 256;            // 0..1023 float4s
            int row = f >> 3, c = f & 7;
            int gr = row0 + row;
            float4 v = make_float4(0.f, 0.f, 0.f, 0.f);
            if (gr < N_TAILN) v = *(const float4*)&A[(size_t)gr * 128 + k0 + c * 4];
            As[c * 4 + 0][row] = v.x;
            As[c * 4 + 1][row] = v.y;
            As[c * 4 + 2][row] = v.z;
            As[c * 4 + 3][row] = v.w;
        }
        __syncthreads();
        #pragma unroll
        for (int k = 0; k < GK; k++) {
            float4 a03 = *(const float4*)&As[k][ti * 8];
            float4 a47 = *(const float4*)&As[k][ti * 8 + 4];
            longlong2 b01 = *(const longlong2*)&Ws[k][tj * 8];
            longlong2 b23 = *(const longlong2*)&Ws[k][tj * 8 + 4];
            unsigned long long aa;
            aa = f2pk(a03.x, a03.x);
            ffma2(acc[0][0], aa, b01.x); ffma2(acc[0][1], aa, b01.y);
            ffma2(acc[0][2], aa, b23.x); ffma2(acc[0][3], aa, b23.y);
            aa = f2pk(a03.y, a03.y);
            ffma2(acc[1][0], aa, b01.x); ffma2(acc[1][1], aa, b01.y);
            ffma2(acc[1][2], aa, b23.x); ffma2(acc[1][3], aa, b23.y);
            aa = f2pk(a03.z, a03.z);
            ffma2(acc[2][0], aa, b01.x); ffma2(acc[2][1], aa, b01.y);
            ffma2(acc[2][2], aa, b23.x); ffma2(acc[2][3], aa, b23.y);
            aa = f2pk(a03.w, a03.w);
            ffma2(acc[3][0], aa, b01.x); ffma2(acc[3][1], aa, b01.y);
            ffma2(acc[3][2], aa, b23.x); ffma2(acc[3][3], aa, b23.y);
            aa = f2pk(a47.x, a47.x);
            ffma2(acc[4][0], aa, b01.x); ffma2(acc[4][1], aa, b01.y);
            ffma2(acc[4][2], aa, b23.x); ffma2(acc[4][3], aa, b23.y);
            aa = f2pk(a47.y, a47.y);
            ffma2(acc[5][0], aa, b01.x); ffma2(acc[5][1], aa, b01.y);
            ffma2(acc[5][2], aa, b23.x); ffma2(acc[5][3], aa, b23.y);
            aa = f2pk(a47.z, a47.z);
            ffma2(acc[6][0], aa, b01.x); ffma2(acc[6][1], aa, b01.y);
            ffma2(acc[6][2], aa, b23.x); ffma2(acc[6][3], aa, b23.y);
            aa = f2pk(a47.w, a47.w);
            ffma2(acc[7][0], aa, b01.x); ffma2(acc[7][1], aa, b01.y);
            ffma2(acc[7][2], aa, b23.x); ffma2(acc[7][3], aa, b23.y);
        }
        __syncthreads();
    }
    #pragma unroll
    for (int r = 0; r < 8; r++) {
        int gr = row0 + ti * 8 + r;
        if (gr < N_TAILN) {
            float2 p0 = f2up(acc[r][0]);
            float2 p1 = f2up(acc[r][1]);
            float2 p2 = f2up(acc[r][2]);
            float2 p3 = f2up(acc[r][3]);
            *(float4*)&g_h_tail[(size_t)gr * 128 + tj * 8] =
                make_float4(p0.x, p0.y, p1.x, p1.y);
            *(float4*)&g_h_tail[(size_t)gr * 128 + tj * 8 + 4] =
                make_float4(p2.x, p2.y, p3.x, p3.y);
        }
    }
}

// ---------------- skinny GEMV: out[n,0..3] = X[n,:] @ M(128x4) ----------------
// 4 threads per node, interleaved float4 reads (fully coalesced), 2 shuffles.
__device__ __forceinline__ void lin128x4(const float* __restrict__ X,
                                         const float* __restrict__ Mg,
                                         float* __restrict__ out, int N) {
    __shared__ float Ms[FDIM * NHEADS];
    int tid = threadIdx.x;
    #pragma unroll
    for (int i = tid; i < FDIM * NHEADS; i += 128) Ms[i] = Mg[i];
    __syncthreads();
    int node = blockIdx.x * 32 + (tid >> 2);
    int sub = tid & 3;
    if (node >= N) return;
    const float* xp = X + (size_t)node * 128;
    float a0 = 0.f, a1 = 0.f, a2 = 0.f, a3 = 0.f;
    #pragma unroll
    for (int q = 0; q < 8; q++) {
        int f4 = sub + 4 * q;
        float4 v = *(const float4*)&xp[f4 * 4];
        const float* m = &Ms[f4 * 16];
        a0 += v.x * m[0] + v.y * m[4] + v.z * m[8]  + v.w * m[12];
        a1 += v.x * m[1] + v.y * m[5] + v.z * m[9]  + v.w * m[13];
        a2 += v.x * m[2] + v.y * m[6] + v.z * m[10] + v.w * m[14];
        a3 += v.x * m[3] + v.y * m[7] + v.z * m[11] + v.w * m[15];
    }
    #pragma unroll
    for (int o = 1; o <= 2; o <<= 1) {
        a0 += __shfl_xor_sync(0xffffffffu, a0, o);
        a1 += __shfl_xor_sync(0xffffffffu, a1, o);
        a2 += __shfl_xor_sync(0xffffffffu, a2, o);
        a3 += __shfl_xor_sync(0xffffffffu, a3, o);
    }
    if (sub == 0)
        *(float4*)&out[(size_t)node * 4] = make_float4(a0, a1, a2, a3);
}

__global__ void __launch_bounds__(128) k_hl(const float* __restrict__ hf) {
    lin128x4(hf, g_WAl, g_hl, N_HEADN);
}
__global__ void __launch_bounds__(128) k_hr() {
    lin128x4(g_h_tail, g_Mr, g_hr, N_TAILN);
}

// ---------------- CSR build --------------------------------------------------
__global__ void k_hist(const int* __restrict__ el) {
    int e = blockIdx.x * blockDim.x + threadIdx.x;
    if (e < NE) atomicAdd(&g_deg[el[e]], 1);
}

__global__ void k_scan() {
    __shared__ int partial[1024];
    int t = threadIdx.x;
    const int CHUNK = (N_HEADN + 1023) / 1024;
    int start = t * CHUNK;
    int end = min(start + CHUNK, N_HEADN);
    int sum = 0;
    for (int i = start; i < end; i++) sum += g_deg[i];
    partial[t] = sum;
    __syncthreads();
    for (int o = 1; o < 1024; o <<= 1) {
        int v = (t >= o) ? partial[t - o] : 0;
        __syncthreads();
        partial[t] += v;
        __syncthreads();
    }
    int run = (t == 0) ? 0 : partial[t - 1];
    for (int i = start; i < end; i++) {
        g_off[i] = run;
        g_cur[i] = run;
        run += g_deg[i];
    }
    if (t == 1023) g_off[N_HEADN] = run;
}

// ---------------- edge: exp(leakyrelu(logit)) scattered into CSR slots -------
__global__ void k_edge(const int* __restrict__ el, const int* __restrict__ et) {
    int e = blockIdx.x * blockDim.x + threadIdx.x;
    if (e >= NE) return;
    int hn = el[e];
    int tn = el[NE + e];
    int ty = et[e];
    float4 l  = *(const float4*)&g_hl[(size_t)hn * 4];
    float4 r  = *(const float4*)&g_hr[(size_t)tn * 4];
    float4 eh = *(const float4*)&g_he[ty * 4];
    float4 a;
    a.x = l.x + r.x + eh.x; if (a.x < 0.f) a.x *= SLOPE;
    a.y = l.y + r.y + eh.y; if (a.y < 0.f) a.y *= SLOPE;
    a.z = l.z + r.z + eh.z; if (a.z < 0.f) a.z *= SLOPE;
    a.w = l.w + r.w + eh.w; if (a.w < 0.f) a.w *= SLOPE;
    a.x = __expf(a.x); a.y = __expf(a.y); a.z = __expf(a.z); a.w = __expf(a.w);
    int pos = atomicAdd(&g_cur[hn], 1);
    *(float4*)&g_wcsr[(size_t)pos * 4] = a;
    g_tl[pos] = tn;
}

// ---------------- node: single-pass normalize + aggregate --------------------
#define CH 128
__global__ void __launch_bounds__(128) k_node(float* __restrict__ out) {
    int n = blockIdx.x;
    int off = g_off[n];
    int deg = g_off[n + 1] - off;
    int tid = threadIdx.x;
    int h = tid >> 5;

    __shared__ int   tl_s[CH];
    __shared__ float ws_s[CH * 4];

    float s0 = 0.f, s1 = 0.f, o0 = 0.f, o1 = 0.f;   // dual accumulators (ILP)
    for (int c0 = 0; c0 < deg; c0 += CH) {
        int cd = min(CH, deg - c0);
        __syncthreads();
        if (tid < cd) {
            tl_s[tid] = g_tl[off + c0 + tid];
            *(float4*)&ws_s[tid * 4] = *(const float4*)&g_wcsr[(size_t)(off + c0 + tid) * 4];
        }
        __syncthreads();
        int j = 0;
        #pragma unroll 2
        for (; j + 1 < cd; j += 2) {
            float wa = ws_s[j * 4 + h];
            float wb = ws_s[(j + 1) * 4 + h];
            float va = g_h_tail[(size_t)tl_s[j] * 128 + tid];
            float vb = g_h_tail[(size_t)tl_s[j + 1] * 128 + tid];
            s0 += wa; o0 += wa * va;
            s1 += wb; o1 += wb * vb;
        }
        if (j < cd) {
            float w = ws_s[j * 4 + h];
            s0 += w;
            o0 += w * g_h_tail[(size_t)tl_s[j] * 128 + tid];
        }
    }
    float s = s0 + s1, outv = o0 + o1;
    float r = (deg > 0) ? outv / s : 0.f;
    out[(size_t)n * 128 + tid] = r > 0.f ? r : expm1f(r);
}

// ---------------- launch -----------------------------------------------------
extern "C" void kernel_launch(void* const* d_in, const int* in_sizes, int n_in,
                              void* d_out, int out_size) {
    const float* head_feature = (const float*)d_in[0];
    const float* tail_feature = (const float*)d_in[1];
    const int*   edge_list    = (const int*)d_in[2];
    const int*   tmp_edge     = (const int*)d_in[3];
    const float* W            = (const float*)d_in[4];
    const float* We           = (const float*)d_in[5];
    const float* a_l          = (const float*)d_in[6];
    const float* a_r          = (const float*)d_in[7];
    const float* a_e          = (const float*)d_in[8];
    const float* emb          = (const float*)d_in[9];
    float* out = (float*)d_out;

    k_setup<<<(N_HEADN + 255) / 256, 256>>>(W, We, a_l, a_r, a_e, emb);
    k_gemm<<<(N_TAILN + 127) / 128, 256>>>(tail_feature, W);
    k_hr<<<(N_TAILN + 31) / 32, 128>>>();
    k_hl<<<(N_HEADN + 31) / 32, 128>>>(head_feature);
    k_hist<<<(NE + 255) / 256, 256>>>(edge_list);
    k_scan<<<1, 1024>>>();
    k_edge<<<(NE + 255) / 256, 256>>>(edge_list, tmp_edge);
    k_node<<<N_HEADN, 128>>>(out);
}

// round 4
// speedup vs baseline: 1.2887x; 1.0257x over previous
#include <cuda_runtime.h>
#include <math.h>

#define N_HEADN 100000
#define N_TAILN 100000
#define NE      1600000
#define NHEADS  4
#define FDIM    128
#define SLOPE   0.2f
#define N_ETYPES 8
#define GK 32

// ---------------- scratch (static device globals; no allocation) -------------
__device__ float g_h_tail[(size_t)N_TAILN * FDIM];   // 51.2 MB
__device__ float g_hl[(size_t)N_HEADN * NHEADS];
__device__ float g_hr[(size_t)N_TAILN * NHEADS];
__device__ float g_he[N_ETYPES * NHEADS];
__device__ float g_WAl[FDIM * NHEADS];               // W folded with a_l
__device__ float g_wcsr[(size_t)NE * NHEADS];        // exp-weights in CSR order
__device__ int   g_tl[NE];                           // tail idx in CSR order
__device__ int   g_deg[N_HEADN];
__device__ int   g_off[N_HEADN + 1];
__device__ int   g_cur[N_HEADN];

// ---------------- f32x2 helpers ----------------------------------------------
__device__ __forceinline__ unsigned long long f2pk(float x, float y) {
    unsigned long long r;
    asm("mov.b64 %0, {%1, %2};" : "=l"(r) : "f"(x), "f"(y));
    return r;
}
__device__ __forceinline__ void ffma2(unsigned long long& d, unsigned long long a,
                                      unsigned long long b) {
    asm("fma.rn.f32x2 %0, %1, %2, %3;" : "=l"(d) : "l"(a), "l"(b), "l"(d));
}
__device__ __forceinline__ float2 f2up(unsigned long long v) {
    float2 r;
    asm("mov.b64 {%0, %1}, %2;" : "=f"(r.x), "=f"(r.y) : "l"(v));
    return r;
}

// ---------------- setup: zero deg, fold a_l into W, compute he ----------------
__global__ void k_setup(const float* __restrict__ W, const float* __restrict__ We,
                        const float* __restrict__ a_l,
                        const float* __restrict__ a_e, const float* __restrict__ emb) {
    int g = blockIdx.x * blockDim.x + threadIdx.x;
    if (g < N_HEADN) g_deg[g] = 0;
    if (blockIdx.x == 0) {
        int t = threadIdx.x;
        if (t < FDIM) {
            #pragma unroll
            for (int h = 0; h < NHEADS; h++) {
                float sl = 0.f;
                #pragma unroll
                for (int d = 0; d < 32; d++)
                    sl += W[t * FDIM + h * 32 + d] * a_l[h * 32 + d];
                g_WAl[t * NHEADS + h] = sl;
            }
        }
        if (t < N_ETYPES * NHEADS) {
            int ty = t >> 2, h = t & 3;
            float s = 0.f;
            for (int de = 0; de < 32; de++) {
                float ev = 0.f;
                for (int k = 0; k < 32; k++)
                    ev += emb[ty * 32 + k] * We[k * 128 + h * 32 + de];
                s += a_e[h * 32 + de] * ev;
            }
            g_he[t] = s;
        }
    }
}

// ---------------- GEMM + fused hr --------------------------------------------
// g_h_tail = tail_feature(1e5 x128) @ W(128x128); epilogue computes
// g_hr[n,h] = dot(row[h*32:h*32+32], a_r[h]) via in-warp reduction.
__global__ void __launch_bounds__(256, 2) k_gemm(const float* __restrict__ A,
                                                 const float* __restrict__ W,
                                                 const float* __restrict__ a_r) {
    __shared__ float Ws[GK][128];    // 16 KB
    __shared__ float As[GK][132];    // 16.9 KB
    int t  = threadIdx.x;
    int ti = t >> 4;                 // 0..15 -> rows ti*8..+7
    int tj = t & 15;                 // 0..15 -> cols tj*8..+7
    int row0 = blockIdx.x * 128;

    unsigned long long acc[8][4];
    #pragma unroll
    for (int r = 0; r < 8; r++)
        #pragma unroll
        for (int c = 0; c < 4; c++) acc[r][c] = f2pk(0.f, 0.f);

    for (int k0 = 0; k0 < 128; k0 += GK) {
        #pragma unroll
        for (int it = 0; it < 4; it++) {
            int f = t + it * 256;
            int k = f >> 5, c4 = f & 31;
            *(float4*)&Ws[k][c4 * 4] = *(const float4*)&W[(k0 + k) * 128 + c4 * 4];
        }
        #pragma unroll
        for (int it = 0; it < 4; it++) {
            int f = t + it * 256;
            int row = f >> 3, c = f & 7;
            int gr = row0 + row;
            float4 v = make_float4(0.f, 0.f, 0.f, 0.f);
            if (gr < N_TAILN) v = *(const float4*)&A[(size_t)gr * 128 + k0 + c * 4];
            As[c * 4 + 0][row] = v.x;
            As[c * 4 + 1][row] = v.y;
            As[c * 4 + 2][row] = v.z;
            As[c * 4 + 3][row] = v.w;
        }
        __syncthreads();
        #pragma unroll
        for (int k = 0; k < GK; k++) {
            float4 a03 = *(const float4*)&As[k][ti * 8];
            float4 a47 = *(const float4*)&As[k][ti * 8 + 4];
            longlong2 b01 = *(const longlong2*)&Ws[k][tj * 8];
            longlong2 b23 = *(const longlong2*)&Ws[k][tj * 8 + 4];
            unsigned long long aa;
            aa = f2pk(a03.x, a03.x);
            ffma2(acc[0][0], aa, b01.x); ffma2(acc[0][1], aa, b01.y);
            ffma2(acc[0][2], aa, b23.x); ffma2(acc[0][3], aa, b23.y);
            aa = f2pk(a03.y, a03.y);
            ffma2(acc[1][0], aa, b01.x); ffma2(acc[1][1], aa, b01.y);
            ffma2(acc[1][2], aa, b23.x); ffma2(acc[1][3], aa, b23.y);
            aa = f2pk(a03.z, a03.z);
            ffma2(acc[2][0], aa, b01.x); ffma2(acc[2][1], aa, b01.y);
            ffma2(acc[2][2], aa, b23.x); ffma2(acc[2][3], aa, b23.y);
            aa = f2pk(a03.w, a03.w);
            ffma2(acc[3][0], aa, b01.x); ffma2(acc[3][1], aa, b01.y);
            ffma2(acc[3][2], aa, b23.x); ffma2(acc[3][3], aa, b23.y);
            aa = f2pk(a47.x, a47.x);
            ffma2(acc[4][0], aa, b01.x); ffma2(acc[4][1], aa, b01.y);
            ffma2(acc[4][2], aa, b23.x); ffma2(acc[4][3], aa, b23.y);
            aa = f2pk(a47.y, a47.y);
            ffma2(acc[5][0], aa, b01.x); ffma2(acc[5][1], aa, b01.y);
            ffma2(acc[5][2], aa, b23.x); ffma2(acc[5][3], aa, b23.y);
            aa = f2pk(a47.z, a47.z);
            ffma2(acc[6][0], aa, b01.x); ffma2(acc[6][1], aa, b01.y);
            ffma2(acc[6][2], aa, b23.x); ffma2(acc[6][3], aa, b23.y);
            aa = f2pk(a47.w, a47.w);
            ffma2(acc[7][0], aa, b01.x); ffma2(acc[7][1], aa, b01.y);
            ffma2(acc[7][2], aa, b23.x); ffma2(acc[7][3], aa, b23.y);
        }
        __syncthreads();
    }
    // a_r slice for this thread's 8 columns (head h = tj>>2)
    int h = tj >> 2;
    float4 ar0 = *(const float4*)&a_r[tj * 8];
    float4 ar1 = *(const float4*)&a_r[tj * 8 + 4];
    #pragma unroll
    for (int r = 0; r < 8; r++) {
        int gr = row0 + ti * 8 + r;
        float2 p0 = f2up(acc[r][0]);
        float2 p1 = f2up(acc[r][1]);
        float2 p2 = f2up(acc[r][2]);
        float2 p3 = f2up(acc[r][3]);
        if (gr < N_TAILN) {
            *(float4*)&g_h_tail[(size_t)gr * 128 + tj * 8] =
                make_float4(p0.x, p0.y, p1.x, p1.y);
            *(float4*)&g_h_tail[(size_t)gr * 128 + tj * 8 + 4] =
                make_float4(p2.x, p2.y, p3.x, p3.y);
        }
        // fused hr: partial dot over this thread's 8 cols, reduce over the
        // 4 lanes sharing head h (lanes are contiguous, group 4-aligned)
        float part = p0.x * ar0.x + p0.y * ar0.y + p1.x * ar0.z + p1.y * ar0.w
                   + p2.x * ar1.x + p2.y * ar1.y + p3.x * ar1.z + p3.y * ar1.w;
        part += __shfl_xor_sync(0xffffffffu, part, 1);
        part += __shfl_xor_sync(0xffffffffu, part, 2);
        if ((tj & 3) == 0 && gr < N_TAILN)
            g_hr[(size_t)gr * 4 + h] = part;
    }
}

// ---------------- hl: out[n,0..3] = head_feature[n,:] @ WAl(128x4) ------------
// 4 threads per node, interleaved float4 streaming reads, 2 shuffles.
__global__ void __launch_bounds__(256) k_hl(const float* __restrict__ hf) {
    __shared__ float Ms[FDIM * NHEADS];
    int tid = threadIdx.x;
    #pragma unroll
    for (int i = tid; i < FDIM * NHEADS; i += 256) Ms[i] = g_WAl[i];
    __syncthreads();
    int node = blockIdx.x * 64 + (tid >> 2);
    int sub = tid & 3;
    if (node >= N_HEADN) return;
    const float4* xp = (const float4*)(hf + (size_t)node * 128);
    float a0 = 0.f, a1 = 0.f, a2 = 0.f, a3 = 0.f;
    #pragma unroll
    for (int q = 0; q < 8; q++) {
        int f4 = sub + 4 * q;
        float4 v = __ldcs(&xp[f4]);
        const float* m = &Ms[f4 * 16];
        a0 += v.x * m[0] + v.y * m[4] + v.z * m[8]  + v.w * m[12];
        a1 += v.x * m[1] + v.y * m[5] + v.z * m[9]  + v.w * m[13];
        a2 += v.x * m[2] + v.y * m[6] + v.z * m[10] + v.w * m[14];
        a3 += v.x * m[3] + v.y * m[7] + v.z * m[11] + v.w * m[15];
    }
    #pragma unroll
    for (int o = 1; o <= 2; o <<= 1) {
        a0 += __shfl_xor_sync(0xffffffffu, a0, o);
        a1 += __shfl_xor_sync(0xffffffffu, a1, o);
        a2 += __shfl_xor_sync(0xffffffffu, a2, o);
        a3 += __shfl_xor_sync(0xffffffffu, a3, o);
    }
    if (sub == 0)
        *(float4*)&g_hl[(size_t)node * 4] = make_float4(a0, a1, a2, a3);
}

// ---------------- CSR build --------------------------------------------------
__global__ void k_hist(const int* __restrict__ el) {
    int e = blockIdx.x * blockDim.x + threadIdx.x;
    if (e < NE) atomicAdd(&g_deg[el[e]], 1);
}

__global__ void k_scan() {
    __shared__ int partial[1024];
    int t = threadIdx.x;
    const int CHUNK = (N_HEADN + 1023) / 1024;
    int start = t * CHUNK;
    int end = min(start + CHUNK, N_HEADN);
    int sum = 0;
    for (int i = start; i < end; i++) sum += g_deg[i];
    partial[t] = sum;
    __syncthreads();
    for (int o = 1; o < 1024; o <<= 1) {
        int v = (t >= o) ? partial[t - o] : 0;
        __syncthreads();
        partial[t] += v;
        __syncthreads();
    }
    int run = (t == 0) ? 0 : partial[t - 1];
    for (int i = start; i < end; i++) {
        g_off[i] = run;
        g_cur[i] = run;
        run += g_deg[i];
    }
    if (t == 1023) g_off[N_HEADN] = run;
}

// ---------------- edge: exp(leakyrelu(logit)) scattered into CSR slots -------
__global__ void k_edge(const int* __restrict__ el, const int* __restrict__ et) {
    int e = blockIdx.x * blockDim.x + threadIdx.x;
    if (e >= NE) return;
    int hn = __ldg(&el[e]);
    int tn = __ldg(&el[NE + e]);
    int ty = __ldg(&et[e]);
    float4 l  = *(const float4*)&g_hl[(size_t)hn * 4];
    float4 r  = *(const float4*)&g_hr[(size_t)tn * 4];
    float4 eh = *(const float4*)&g_he[ty * 4];
    float4 a;
    a.x = l.x + r.x + eh.x; if (a.x < 0.f) a.x *= SLOPE;
    a.y = l.y + r.y + eh.y; if (a.y < 0.f) a.y *= SLOPE;
    a.z = l.z + r.z + eh.z; if (a.z < 0.f) a.z *= SLOPE;
    a.w = l.w + r.w + eh.w; if (a.w < 0.f) a.w *= SLOPE;
    a.x = __expf(a.x); a.y = __expf(a.y); a.z = __expf(a.z); a.w = __expf(a.w);
    int pos = atomicAdd(&g_cur[hn], 1);
    *(float4*)&g_wcsr[(size_t)pos * 4] = a;
    g_tl[pos] = tn;
}

// ---------------- node: single-pass normalize + aggregate --------------------
#define CH 128
__global__ void __launch_bounds__(128) k_node(float* __restrict__ out) {
    int n = blockIdx.x;
    int off = g_off[n];
    int deg = g_off[n + 1] - off;
    int tid = threadIdx.x;
    int h = tid >> 5;

    __shared__ int   tl_s[CH];
    __shared__ float ws_s[CH * 4];

    float s0 = 0.f, s1 = 0.f, s2 = 0.f, s3 = 0.f;
    float o0 = 0.f, o1 = 0.f, o2 = 0.f, o3 = 0.f;
    for (int c0 = 0; c0 < deg; c0 += CH) {
        int cd = min(CH, deg - c0);
        __syncthreads();
        if (tid < cd) {
            tl_s[tid] = g_tl[off + c0 + tid];
            *(float4*)&ws_s[tid * 4] = *(const float4*)&g_wcsr[(size_t)(off + c0 + tid) * 4];
        }
        __syncthreads();
        int j = 0;
        for (; j + 3 < cd; j += 4) {
            float wa = ws_s[(j + 0) * 4 + h];
            float wb = ws_s[(j + 1) * 4 + h];
            float wc = ws_s[(j + 2) * 4 + h];
            float wd = ws_s[(j + 3) * 4 + h];
            float va = g_h_tail[(size_t)tl_s[j + 0] * 128 + tid];
            float vb = g_h_tail[(size_t)tl_s[j + 1] * 128 + tid];
            float vc = g_h_tail[(size_t)tl_s[j + 2] * 128 + tid];
            float vd = g_h_tail[(size_t)tl_s[j + 3] * 128 + tid];
            s0 += wa; o0 += wa * va;
            s1 += wb; o1 += wb * vb;
            s2 += wc; o2 += wc * vc;
            s3 += wd; o3 += wd * vd;
        }
        for (; j < cd; j++) {
            float w = ws_s[j * 4 + h];
            s0 += w;
            o0 += w * g_h_tail[(size_t)tl_s[j] * 128 + tid];
        }
    }
    float s = (s0 + s1) + (s2 + s3);
    float outv = (o0 + o1) + (o2 + o3);
    float r = (deg > 0) ? outv / s : 0.f;
    out[(size_t)n * 128 + tid] = r > 0.f ? r : expm1f(r);
}

// ---------------- launch -----------------------------------------------------
extern "C" void kernel_launch(void* const* d_in, const int* in_sizes, int n_in,
                              void* d_out, int out_size) {
    const float* head_feature = (const float*)d_in[0];
    const float* tail_feature = (const float*)d_in[1];
    const int*   edge_list    = (const int*)d_in[2];
    const int*   tmp_edge     = (const int*)d_in[3];
    const float* W            = (const float*)d_in[4];
    const float* We           = (const float*)d_in[5];
    const float* a_l          = (const float*)d_in[6];
    const float* a_r          = (const float*)d_in[7];
    const float* a_e          = (const float*)d_in[8];
    const float* emb          = (const float*)d_in[9];
    float* out = (float*)d_out;

    k_setup<<<(N_HEADN + 255) / 256, 256>>>(W, We, a_l, a_e, emb);
    k_gemm<<<(N_TAILN + 127) / 128, 256>>>(tail_feature, W, a_r);
    k_hl<<<(N_HEADN + 63) / 64, 256>>>(head_feature);
    k_hist<<<(NE + 255) / 256, 256>>>(edge_list);
    k_scan<<<1, 1024>>>();
    k_edge<<<(NE + 255) / 256, 256>>>(edge_list, tmp_edge);
    k_node<<<N_HEADN, 128>>>(out);
}

// round 7
// speedup vs baseline: 1.4866x; 1.1536x over previous
#include <cuda_runtime.h>
#include <math.h>

#define N_HEADN 100000
#define N_TAILN 100000
#define NE      1600000
#define NHEADS  4
#define FDIM    128
#define SLOPE   0.2f
#define N_ETYPES 8
#define GK 32
#define FULLM 0xffffffffu

// ---------------- scratch (static device globals; no allocation) -------------
__device__ float g_h_tail[(size_t)N_TAILN * FDIM];   // 51.2 MB
__device__ float g_hl[(size_t)N_HEADN * NHEADS];
__device__ float g_hr[(size_t)N_TAILN * NHEADS];
__device__ float g_he[N_ETYPES * NHEADS];
__device__ float g_WAl[FDIM * NHEADS];               // W folded with a_l
__device__ float g_wcsr[(size_t)NE * NHEADS];        // exp-weights in CSR order
__device__ int   g_tl[NE];                           // tail idx in CSR order
__device__ int   g_deg[N_HEADN];
__device__ int   g_off[N_HEADN + 1];
__device__ int   g_cur[N_HEADN];

// ---------------- f32x2 helpers ----------------------------------------------
__device__ __forceinline__ unsigned long long f2pk(float x, float y) {
    unsigned long long r;
    asm("mov.b64 %0, {%1, %2};" : "=l"(r) : "f"(x), "f"(y));
    return r;
}
__device__ __forceinline__ void ffma2(unsigned long long& d, unsigned long long a,
                                      unsigned long long b) {
    asm("fma.rn.f32x2 %0, %1, %2, %3;" : "=l"(d) : "l"(a), "l"(b), "l"(d));
}
__device__ __forceinline__ float2 f2up(unsigned long long v) {
    float2 r;
    asm("mov.b64 {%0, %1}, %2;" : "=f"(r.x), "=f"(r.y) : "l"(v));
    return r;
}

// ---------------- setup: zero deg, fold a_l into W, compute he ----------------
__global__ void k_setup(const float* __restrict__ W, const float* __restrict__ We,
                        const float* __restrict__ a_l,
                        const float* __restrict__ a_e, const float* __restrict__ emb) {
    int g = blockIdx.x * blockDim.x + threadIdx.x;
    if (g < N_HEADN) g_deg[g] = 0;
    if (blockIdx.x == 0) {
        int t = threadIdx.x;
        if (t < FDIM) {
            #pragma unroll
            for (int h = 0; h < NHEADS; h++) {
                float sl = 0.f;
                #pragma unroll
                for (int d = 0; d < 32; d++)
                    sl += W[t * FDIM + h * 32 + d] * a_l[h * 32 + d];
                g_WAl[t * NHEADS + h] = sl;
            }
        }
        if (t < N_ETYPES * NHEADS) {
            int ty = t >> 2, h = t & 3;
            float s = 0.f;
            for (int de = 0; de < 32; de++) {
                float ev = 0.f;
                for (int k = 0; k < 32; k++)
                    ev += emb[ty * 32 + k] * We[k * 128 + h * 32 + de];
                s += a_e[h * 32 + de] * ev;
            }
            g_he[t] = s;
        }
    }
}

// ---------------- GEMM + fused hr --------------------------------------------
__global__ void __launch_bounds__(256, 2) k_gemm(const float* __restrict__ A,
                                                 const float* __restrict__ W,
                                                 const float* __restrict__ a_r) {
    __shared__ float Ws[GK][128];
    __shared__ float As[GK][132];
    int t  = threadIdx.x;
    int ti = t >> 4;
    int tj = t & 15;
    int row0 = blockIdx.x * 128;

    unsigned long long acc[8][4];
    #pragma unroll
    for (int r = 0; r < 8; r++)
        #pragma unroll
        for (int c = 0; c < 4; c++) acc[r][c] = f2pk(0.f, 0.f);

    for (int k0 = 0; k0 < 128; k0 += GK) {
        #pragma unroll
        for (int it = 0; it < 4; it++) {
            int f = t + it * 256;
            int k = f >> 5, c4 = f & 31;
            *(float4*)&Ws[k][c4 * 4] = *(const float4*)&W[(k0 + k) * 128 + c4 * 4];
        }
        #pragma unroll
        for (int it = 0; it < 4; it++) {
            int f = t + it * 256;
            int row = f >> 3, c = f & 7;
            int gr = row0 + row;
            float4 v = make_float4(0.f, 0.f, 0.f, 0.f);
            if (gr < N_TAILN) v = __ldcs((const float4*)&A[(size_t)gr * 128 + k0 + c * 4]);
            As[c * 4 + 0][row] = v.x;
            As[c * 4 + 1][row] = v.y;
            As[c * 4 + 2][row] = v.z;
            As[c * 4 + 3][row] = v.w;
        }
        __syncthreads();
        #pragma unroll
        for (int k = 0; k < GK; k++) {
            float4 a03 = *(const float4*)&As[k][ti * 8];
            float4 a47 = *(const float4*)&As[k][ti * 8 + 4];
            longlong2 b01 = *(const longlong2*)&Ws[k][tj * 8];
            longlong2 b23 = *(const longlong2*)&Ws[k][tj * 8 + 4];
            unsigned long long aa;
            aa = f2pk(a03.x, a03.x);
            ffma2(acc[0][0], aa, b01.x); ffma2(acc[0][1], aa, b01.y);
            ffma2(acc[0][2], aa, b23.x); ffma2(acc[0][3], aa, b23.y);
            aa = f2pk(a03.y, a03.y);
            ffma2(acc[1][0], aa, b01.x); ffma2(acc[1][1], aa, b01.y);
            ffma2(acc[1][2], aa, b23.x); ffma2(acc[1][3], aa, b23.y);
            aa = f2pk(a03.z, a03.z);
            ffma2(acc[2][0], aa, b01.x); ffma2(acc[2][1], aa, b01.y);
            ffma2(acc[2][2], aa, b23.x); ffma2(acc[2][3], aa, b23.y);
            aa = f2pk(a03.w, a03.w);
            ffma2(acc[3][0], aa, b01.x); ffma2(acc[3][1], aa, b01.y);
            ffma2(acc[3][2], aa, b23.x); ffma2(acc[3][3], aa, b23.y);
            aa = f2pk(a47.x, a47.x);
            ffma2(acc[4][0], aa, b01.x); ffma2(acc[4][1], aa, b01.y);
            ffma2(acc[4][2], aa, b23.x); ffma2(acc[4][3], aa, b23.y);
            aa = f2pk(a47.y, a47.y);
            ffma2(acc[5][0], aa, b01.x); ffma2(acc[5][1], aa, b01.y);
            ffma2(acc[5][2], aa, b23.x); ffma2(acc[5][3], aa, b23.y);
            aa = f2pk(a47.z, a47.z);
            ffma2(acc[6][0], aa, b01.x); ffma2(acc[6][1], aa, b01.y);
            ffma2(acc[6][2], aa, b23.x); ffma2(acc[6][3], aa, b23.y);
            aa = f2pk(a47.w, a47.w);
            ffma2(acc[7][0], aa, b01.x); ffma2(acc[7][1], aa, b01.y);
            ffma2(acc[7][2], aa, b23.x); ffma2(acc[7][3], aa, b23.y);
        }
        __syncthreads();
    }
    int h = tj >> 2;
    float4 ar0 = *(const float4*)&a_r[tj * 8];
    float4 ar1 = *(const float4*)&a_r[tj * 8 + 4];
    #pragma unroll
    for (int r = 0; r < 8; r++) {
        int gr = row0 + ti * 8 + r;
        float2 p0 = f2up(acc[r][0]);
        float2 p1 = f2up(acc[r][1]);
        float2 p2 = f2up(acc[r][2]);
        float2 p3 = f2up(acc[r][3]);
        if (gr < N_TAILN) {
            *(float4*)&g_h_tail[(size_t)gr * 128 + tj * 8] =
                make_float4(p0.x, p0.y, p1.x, p1.y);
            *(float4*)&g_h_tail[(size_t)gr * 128 + tj * 8 + 4] =
                make_float4(p2.x, p2.y, p3.x, p3.y);
        }
        float part = p0.x * ar0.x + p0.y * ar0.y + p1.x * ar0.z + p1.y * ar0.w
                   + p2.x * ar1.x + p2.y * ar1.y + p3.x * ar1.z + p3.y * ar1.w;
        part += __shfl_xor_sync(FULLM, part, 1);
        part += __shfl_xor_sync(FULLM, part, 2);
        if ((tj & 3) == 0 && gr < N_TAILN)
            g_hr[(size_t)gr * 4 + h] = part;
    }
}

// ---------------- hl: out[n,0..3] = head_feature[n,:] @ WAl(128x4) ------------
__global__ void __launch_bounds__(256) k_hl(const float* __restrict__ hf) {
    __shared__ float Ms[FDIM * NHEADS];
    int tid = threadIdx.x;
    #pragma unroll
    for (int i = tid; i < FDIM * NHEADS; i += 256) Ms[i] = g_WAl[i];
    __syncthreads();
    int node = blockIdx.x * 64 + (tid >> 2);
    int sub = tid & 3;
    if (node >= N_HEADN) return;
    const float4* xp = (const float4*)(hf + (size_t)node * 128);
    float a0 = 0.f, a1 = 0.f, a2 = 0.f, a3 = 0.f;
    #pragma unroll
    for (int q = 0; q < 8; q++) {
        int f4 = sub + 4 * q;
        float4 v = __ldcs(&xp[f4]);
        const float* m = &Ms[f4 * 16];
        a0 += v.x * m[0] + v.y * m[4] + v.z * m[8]  + v.w * m[12];
        a1 += v.x * m[1] + v.y * m[5] + v.z * m[9]  + v.w * m[13];
        a2 += v.x * m[2] + v.y * m[6] + v.z * m[10] + v.w * m[14];
        a3 += v.x * m[3] + v.y * m[7] + v.z * m[11] + v.w * m[15];
    }
    #pragma unroll
    for (int o = 1; o <= 2; o <<= 1) {
        a0 += __shfl_xor_sync(FULLM, a0, o);
        a1 += __shfl_xor_sync(FULLM, a1, o);
        a2 += __shfl_xor_sync(FULLM, a2, o);
        a3 += __shfl_xor_sync(FULLM, a3, o);
    }
    if (sub == 0)
        *(float4*)&g_hl[(size_t)node * 4] = make_float4(a0, a1, a2, a3);
}

// ---------------- CSR build --------------------------------------------------
__global__ void k_hist(const int* __restrict__ el) {
    int e = blockIdx.x * blockDim.x + threadIdx.x;
    if (e < NE) atomicAdd(&g_deg[el[e]], 1);
}

__global__ void k_scan() {
    __shared__ int partial[1024];
    int t = threadIdx.x;
    const int CHUNK = (N_HEADN + 1023) / 1024;
    int start = t * CHUNK;
    int end = min(start + CHUNK, N_HEADN);
    int sum = 0;
    for (int i = start; i < end; i++) sum += g_deg[i];
    partial[t] = sum;
    __syncthreads();
    for (int o = 1; o < 1024; o <<= 1) {
        int v = (t >= o) ? partial[t - o] : 0;
        __syncthreads();
        partial[t] += v;
        __syncthreads();
    }
    int run = (t == 0) ? 0 : partial[t - 1];
    for (int i = start; i < end; i++) {
        g_off[i] = run;
        g_cur[i] = run;
        run += g_deg[i];
    }
    if (t == 1023) g_off[N_HEADN] = run;
}

// ---------------- edge: exp(leakyrelu(logit)) scattered into CSR slots -------
__global__ void k_edge(const int* __restrict__ el, const int* __restrict__ et) {
    int e = blockIdx.x * blockDim.x + threadIdx.x;
    if (e >= NE) return;
    int hn = __ldg(&el[e]);
    int tn = __ldg(&el[NE + e]);
    int ty = __ldg(&et[e]);
    float4 l  = *(const float4*)&g_hl[(size_t)hn * 4];
    float4 r  = *(const float4*)&g_hr[(size_t)tn * 4];
    float4 eh = *(const float4*)&g_he[ty * 4];
    float4 a;
    a.x = l.x + r.x + eh.x; if (a.x < 0.f) a.x *= SLOPE;
    a.y = l.y + r.y + eh.y; if (a.y < 0.f) a.y *= SLOPE;
    a.z = l.z + r.z + eh.z; if (a.z < 0.f) a.z *= SLOPE;
    a.w = l.w + r.w + eh.w; if (a.w < 0.f) a.w *= SLOPE;
    a.x = __expf(a.x); a.y = __expf(a.y); a.z = __expf(a.z); a.w = __expf(a.w);
    int pos = atomicAdd(&g_cur[hn], 1);
    *(float4*)&g_wcsr[(size_t)pos * 4] = a;
    g_tl[pos] = tn;
}

// ---------------- node: warp-per-node, no smem, no barriers -------------------
// lane covers features 4*lane..4*lane+3 (head = lane>>3). Per 32-edge batch:
// tail ids + 128 weights loaded coalesced into registers, distributed by shfl.
__global__ void __launch_bounds__(128) k_node(float* __restrict__ out) {
    int n = blockIdx.x * 4 + (threadIdx.x >> 5);
    if (n >= N_HEADN) return;
    int lane = threadIdx.x & 31;
    int h = lane >> 3;
    int off = g_off[n];
    int deg = g_off[n + 1] - off;

    float4 acc = make_float4(0.f, 0.f, 0.f, 0.f);
    float s = 0.f;

    for (int b0 = 0; b0 < deg; b0 += 32) {
        int e32 = min(32, deg - b0);
        int tl_v = (lane < e32) ? g_tl[off + b0 + lane] : 0;
        const float* wbase = &g_wcsr[(size_t)(off + b0) * 4];
        int tot = e32 * 4;
        float w0 = (lane < tot)      ? wbase[lane]      : 0.f;
        float w1 = (lane + 32 < tot) ? wbase[lane + 32] : 0.f;
        float w2 = (lane + 64 < tot) ? wbase[lane + 64] : 0.f;
        float w3 = (lane + 96 < tot) ? wbase[lane + 96] : 0.f;

        int j = 0;
        for (; j + 3 < e32; j += 4) {
            int t0 = __shfl_sync(FULLM, tl_v, j + 0);
            int t1 = __shfl_sync(FULLM, tl_v, j + 1);
            int t2 = __shfl_sync(FULLM, tl_v, j + 2);
            int t3 = __shfl_sync(FULLM, tl_v, j + 3);
            float4 v0 = *(const float4*)&g_h_tail[(size_t)t0 * 128 + lane * 4];
            float4 v1 = *(const float4*)&g_h_tail[(size_t)t1 * 128 + lane * 4];
            float4 v2 = *(const float4*)&g_h_tail[(size_t)t2 * 128 + lane * 4];
            float4 v3 = *(const float4*)&g_h_tail[(size_t)t3 * 128 + lane * 4];
            // bank = j>>3, constant across j..j+3 (j multiple of 4)
            float bank0 = (j < 8) ? w0 : (j < 16) ? w1 : (j < 24) ? w2 : w3;
            float wa = __shfl_sync(FULLM, bank0, ((j + 0) * 4 + h) & 31);
            float wb = __shfl_sync(FULLM, bank0, ((j + 1) * 4 + h) & 31);
            float wc = __shfl_sync(FULLM, bank0, ((j + 2) * 4 + h) & 31);
            float wd = __shfl_sync(FULLM, bank0, ((j + 3) * 4 + h) & 31);
            acc.x += wa * v0.x; acc.y += wa * v0.y; acc.z += wa * v0.z; acc.w += wa * v0.w;
            acc.x += wb * v1.x; acc.y += wb * v1.y; acc.z += wb * v1.z; acc.w += wb * v1.w;
            acc.x += wc * v2.x; acc.y += wc * v2.y; acc.z += wc * v2.z; acc.w += wc * v2.w;
            acc.x += wd * v3.x; acc.y += wd * v3.y; acc.z += wd * v3.z; acc.w += wd * v3.w;
            s += wa + wb + wc + wd;
        }
        for (; j < e32; j++) {
            int tn = __shfl_sync(FULLM, tl_v, j);
            float bank = (j < 8) ? w0 : (j < 16) ? w1 : (j < 24) ? w2 : w3;
            float w = __shfl_sync(FULLM, bank, (j * 4 + h) & 31);
            float4 v = *(const float4*)&g_h_tail[(size_t)tn * 128 + lane * 4];
            acc.x += w * v.x; acc.y += w * v.y; acc.z += w * v.z; acc.w += w * v.w;
            s += w;
        }
    }

    float4 r;
    if (deg > 0) {
        float inv = 1.f / s;
        r.x = acc.x * inv; r.y = acc.y * inv; r.z = acc.z * inv; r.w = acc.w * inv;
    } else {
        r = make_float4(0.f, 0.f, 0.f, 0.f);
    }
    r.x = r.x > 0.f ? r.x : expm1f(r.x);
    r.y = r.y > 0.f ? r.y : expm1f(r.y);
    r.z = r.z > 0.f ? r.z : expm1f(r.z);
    r.w = r.w > 0.f ? r.w : expm1f(r.w);
    *(float4*)&out[(size_t)n * 128 + lane * 4] = r;
}

// ---------------- launch -----------------------------------------------------
extern "C" void kernel_launch(void* const* d_in, const int* in_sizes, int n_in,
                              void* d_out, int out_size) {
    const float* head_feature = (const float*)d_in[0];
    const float* tail_feature = (const float*)d_in[1];
    const int*   edge_list    = (const int*)d_in[2];
    const int*   tmp_edge     = (const int*)d_in[3];
    const float* W            = (const float*)d_in[4];
    const float* We           = (const float*)d_in[5];
    const float* a_l          = (const float*)d_in[6];
    const float* a_r          = (const float*)d_in[7];
    const float* a_e          = (const float*)d_in[8];
    const float* emb          = (const float*)d_in[9];
    float* out = (float*)d_out;

    k_setup<<<(N_HEADN + 255) / 256, 256>>>(W, We, a_l, a_e, emb);
    k_gemm<<<(N_TAILN + 127) / 128, 256>>>(tail_feature, W, a_r);
    k_hl<<<(N_HEADN + 63) / 64, 256>>>(head_feature);
    k_hist<<<(NE + 255) / 256, 256>>>(edge_list);
    k_scan<<<1, 1024>>>();
    k_edge<<<(NE + 255) / 256, 256>>>(edge_list, tmp_edge);
    k_node<<<(N_HEADN + 3) / 4, 128>>>(out);
}